// round 17
// baseline (speedup 1.0000x reference)
#include <cuda_runtime.h>
#include <cuda_bf16.h>
#include <cuda_fp16.h>
#include <cstdint>
#include <math.h>

// Problem constants
#define B_    2
#define S_    2048
#define HID_  2048
#define H_    16
#define KV_   8
#define D_    128
#define GROUPS (H_ / KV_)   // 2
#define MROWS (B_ * S_)     // 4096
#define NQKV  ((H_ + 2 * KV_) * D_)   // 4096
#define NQT   (S_ / 128)    // 16 q-tiles
#define NITEMS (NQT * H_ * B_)  // 512 flash work items

// Scratch (device globals: allocation-free per harness rules)
__device__ __half g_qh[(size_t)B_ * H_ * S_ * D_];  // post rmsnorm+rope, *SCALE
__device__ __half g_kh[(size_t)B_ * KV_ * S_ * D_]; // post rmsnorm+rope
__device__ __half g_vh[(size_t)B_ * KV_ * S_ * D_]; // v, fp16
__device__ __half g_xh[(size_t)MROWS * HID_];
__device__ __half g_atth[(size_t)MROWS * (H_ * D_)];
__device__ __half g_wallh[(size_t)NQKV * HID_];
__device__ __half g_woh[(size_t)HID_ * (H_ * D_)];
__device__ int g_fctr;

// ---------------------------------------------------------------------------
// Portable PTX helpers (compute_103 — no 'a'-target features)
// ---------------------------------------------------------------------------
__device__ __forceinline__ uint32_t smem_to_u32(const void* p) {
    uint32_t a;
    asm("{ .reg .u64 t; cvta.to.shared.u64 t, %1; cvt.u32.u64 %0, t; }" : "=r"(a) : "l"(p));
    return a;
}
__device__ __forceinline__ void cp_async16(uint32_t s, const void* g) {
    asm volatile("cp.async.cg.shared.global [%0], [%1], 16;" :: "r"(s), "l"(g));
}
#define CP_COMMIT() asm volatile("cp.async.commit_group;" ::: "memory")
#define CP_WAIT1()  asm volatile("cp.async.wait_group 1;"  ::: "memory")
#define CP_WAIT0()  asm volatile("cp.async.wait_group 0;"  ::: "memory")

#define LDSM_X4(R, addr) \
    asm volatile("ldmatrix.sync.aligned.m8n8.x4.shared.b16 {%0,%1,%2,%3}, [%4];" \
        : "=r"((R)[0]), "=r"((R)[1]), "=r"((R)[2]), "=r"((R)[3]) : "r"(addr))
#define LDSM_X4_T(R, addr) \
    asm volatile("ldmatrix.sync.aligned.m8n8.x4.trans.shared.b16 {%0,%1,%2,%3}, [%4];" \
        : "=r"((R)[0]), "=r"((R)[1]), "=r"((R)[2]), "=r"((R)[3]) : "r"(addr))

__device__ __forceinline__ void mma_f16(float* d, const uint32_t* a, uint32_t b0, uint32_t b1) {
    asm volatile(
        "mma.sync.aligned.m16n8k16.row.col.f32.f16.f16.f32 "
        "{%0,%1,%2,%3}, {%4,%5,%6,%7}, {%8,%9}, {%0,%1,%2,%3};"
        : "+f"(d[0]), "+f"(d[1]), "+f"(d[2]), "+f"(d[3])
        : "r"(a[0]), "r"(a[1]), "r"(a[2]), "r"(a[3]), "r"(b0), "r"(b1));
}

__device__ __forceinline__ uint32_t pack_half2(float a, float b) {
    __half2 h = __floats2half2_rn(a, b);
    return *(uint32_t*)&h;
}

// ---------------------------------------------------------------------------
// Fused prep kernel: region-dispatched; also resets the flash work counter.
// ---------------------------------------------------------------------------
__global__ __launch_bounds__(256)
void prep_all(const float* __restrict__ x, __half* __restrict__ xh,
              const float* __restrict__ W0, __half* __restrict__ D0,
              const float* __restrict__ W1, __half* __restrict__ D1,
              const float* __restrict__ W2, __half* __restrict__ D2,
              const float* __restrict__ W3, __half* __restrict__ D3)
{
    const int tid = threadIdx.y * 32 + threadIdx.x;
    int bid = blockIdx.x;
    if (bid == 0 && tid == 0) g_fctr = 0;
    if (bid < 8192) {
        size_t i = ((size_t)bid * 256 + tid) * 4;
        float4 v = *(const float4*)(x + i);
        *(__half2*)(xh + i)     = __floats2half2_rn(v.x, v.y);
        *(__half2*)(xh + i + 2) = __floats2half2_rn(v.z, v.w);
        return;
    }
    bid -= 8192;
    __shared__ float t[32][33];
    const float* W; __half* Dst; int N;
    const int K = 2048;
    if (bid < 4096)      { W = W0; Dst = D0; N = 2048; }
    else if (bid < 6144) { W = W1; Dst = D1; N = 1024; bid -= 4096; }
    else if (bid < 8192) { W = W2; Dst = D2; N = 1024; bid -= 6144; }
    else                 { W = W3; Dst = D3; N = 2048; bid -= 8192; }
    int tn = N >> 5;
    int n0 = (bid % tn) * 32, k0 = (bid / tn) * 32;
    int tx = threadIdx.x, ty = threadIdx.y;      // 32 x 8
    #pragma unroll
    for (int i = 0; i < 32; i += 8)
        t[ty + i][tx] = W[(size_t)(k0 + ty + i) * N + n0 + tx];
    __syncthreads();
    #pragma unroll
    for (int i = 0; i < 32; i += 8)
        Dst[(size_t)(n0 + ty + i) * K + k0 + tx] = __float2half(t[tx][ty + i]);
}

// ---------------------------------------------------------------------------
// Single-pass fp16 GEMM, CTA 128x256, warp tile 64x64, BK=64, 3-stage pipe,
// occ-1 (regs for deep ILP). mode 0: C fp32. mode 4: fused QKV with
// in-epilogue RMSNorm+RoPE (bitwise-identical row math to rmsrope3).
// ---------------------------------------------------------------------------
#define BM 128
#define BN 256
#define GROWB 144
#define GATILE (128 * GROWB)         // 18432  (A: 128 rows)
#define GBTILE (256 * GROWB)         // 36864  (B: 256 rows)
#define GST_B (GATILE + GBTILE)      // 55296 per stage
#define GEMM_SMEM (3 * GST_B)        // 165888
#define EROW 264                     // epilogue staging row stride (floats)

__global__ __launch_bounds__(256, 1)
void gemm_f16(const __half* __restrict__ Ah, const __half* __restrict__ Bh,
              float* __restrict__ C, int M, int Ndim, int Kdim, int mode,
              const float* __restrict__ qw, const float* __restrict__ kw,
              const float* __restrict__ sinp, const float* __restrict__ cosp)
{
    constexpr int AHO = 0;
    constexpr int BHO = GATILE;

    extern __shared__ char sm[];
    const uint32_t sbase = smem_to_u32(sm);
    const int tid = threadIdx.x;
    const int wid = tid >> 5;
    const int lane = tid & 31;
    const int m0 = blockIdx.y * BM;
    const int n0 = blockIdx.x * BN;
    const int wm = (wid & 1) * 64;          // 2 warps in m
    const int wn = (wid >> 1) * 64;         // 4 warps in n, 64 cols each

    float acc[4][8][4];
    #pragma unroll
    for (int i = 0; i < 4; i++)
        #pragma unroll
        for (int j = 0; j < 8; j++)
            #pragma unroll
            for (int q = 0; q < 4; q++) acc[i][j][q] = 0.f;

    const int kchunks = Kdim / 64;

    auto load_stage = [&](int s, int c) {
        const uint32_t so = sbase + (uint32_t)(s * GST_B);
        const __half* pAh = Ah + (size_t)m0 * Kdim + c * 64;
        const __half* pBh = Bh + (size_t)n0 * Kdim + c * 64;
        #pragma unroll
        for (int u = 0; u < 4; u++) {
            int f = tid + u * 256;          // 0..1023
            int r = f >> 3, g = f & 7;
            cp_async16(so + (uint32_t)(AHO + r * GROWB + g * 16),
                       pAh + (size_t)r * Kdim + g * 8);
        }
        #pragma unroll
        for (int u = 0; u < 8; u++) {
            int f = tid + u * 256;          // 0..2047
            int r = f >> 3, g = f & 7;
            cp_async16(so + (uint32_t)(BHO + r * GROWB + g * 16),
                       pBh + (size_t)r * Kdim + g * 8);
        }
    };

    load_stage(0, 0);
    CP_COMMIT();
    load_stage(1, 1);
    CP_COMMIT();

    const int rowA = lane & 15;
    const uint32_t aoffs = (uint32_t)((wm + rowA) * GROWB + ((lane >> 4) << 4));
    const int rowB = (lane & 7) + ((lane >> 4) << 3);
    const uint32_t boffs = (uint32_t)((wn + rowB) * GROWB + (((lane >> 3) & 1) << 4));

    int cur = 0, nxt2 = 2;
    for (int c = 0; c < kchunks; c++) {
        CP_WAIT1();
        __syncthreads();
        if (c + 2 < kchunks) load_stage(nxt2, c + 2);
        CP_COMMIT();

        const uint32_t base = sbase + (uint32_t)(cur * GST_B);

        #pragma unroll
        for (int t = 0; t < 4; t++) {
            uint32_t ah[4][4], bb[8][2];
            #pragma unroll
            for (int p = 0; p < 4; p++) {   // 64 B-rows = 4 LDSM
                uint32_t r[4];
                LDSM_X4(r, base + BHO + boffs + p * (16 * GROWB) + t * 32);
                bb[2 * p][0] = r[0]; bb[2 * p][1] = r[1];
                bb[2 * p + 1][0] = r[2]; bb[2 * p + 1][1] = r[3];
            }
            #pragma unroll
            for (int mt = 0; mt < 4; mt++)
                LDSM_X4(ah[mt], base + AHO + aoffs + mt * (16 * GROWB) + t * 32);
            #pragma unroll
            for (int mt = 0; mt < 4; mt++)
                #pragma unroll
                for (int nt = 0; nt < 8; nt++)
                    mma_f16(acc[mt][nt], ah[mt], bb[nt][0], bb[nt][1]);
        }

        cur = (cur == 2) ? 0 : cur + 1;
        nxt2 = (nxt2 == 2) ? 0 : nxt2 + 1;
    }

    const int fr = lane >> 2;
    const int c2 = (lane & 3) * 2;

    const bool qkreg = (mode == 4) && (n0 < (H_ + KV_) * D_);

    if (!qkreg) {
        // direct epilogue: mode 0 (C fp32) or V region (fp16)
        #pragma unroll
        for (int mt = 0; mt < 4; mt++) {
            #pragma unroll
            for (int half = 0; half < 2; half++) {
                int m = m0 + wm + mt * 16 + fr + half * 8;
                int bb2 = m >> 11;              // S_ = 2048
                int s = m & 2047;
                #pragma unroll
                for (int nt = 0; nt < 8; nt++) {
                    int n = n0 + wn + nt * 8 + c2;
                    float2 v = make_float2(acc[mt][nt][half * 2], acc[mt][nt][half * 2 + 1]);
                    if (mode == 0) {
                        *(float2*)(C + (size_t)m * Ndim + n) = v;
                    } else {
                        int nn = n - (H_ + KV_) * D_;
                        int h = nn >> 7, d0 = nn & 127;
                        __half2 hv = __floats2half2_rn(v.x, v.y);
                        *(__half2*)(g_vh + (((size_t)(bb2 * KV_ + h) * S_ + s) * D_) + d0) = hv;
                    }
                }
            }
        }
        return;
    }

    // Q/K region: stage acc tile (128 x 256) to smem, fused RMSNorm + RoPE
    float* es = (float*)sm;                 // [128][EROW] fp32 = 135 KB
    __syncthreads();                        // mainloop smem reads done
    #pragma unroll
    for (int mt = 0; mt < 4; mt++) {
        #pragma unroll
        for (int half = 0; half < 2; half++) {
            int r = wm + mt * 16 + fr + half * 8;
            #pragma unroll
            for (int nt = 0; nt < 8; nt++) {
                int col = wn + nt * 8 + c2;
                *(float2*)&es[r * EROW + col] =
                    make_float2(acc[mt][nt][half * 2], acc[mt][nt][half * 2 + 1]);
            }
        }
    }
    __syncthreads();

    const int isQ = (n0 < H_ * D_);
    const float* w = isQ ? qw : kw;
    __half* outp = isQ ? g_qh : g_kh;
    const int nh = isQ ? H_ : KV_;
    const float postscale = isQ ? 0.08838834764831845f : 1.0f;
    const int hbase = isQ ? (n0 >> 7) : ((n0 - H_ * D_) >> 7);

    const float4 wv = *(const float4*)(w + lane * 4);

    // 2 heads per tile (256 cols); per-row math identical to rmsrope3
    #pragma unroll 1
    for (int hp = 0; hp < 2; hp++) {
        const int hh = hbase + hp;
        #pragma unroll 1
        for (int rr = 0; rr < 16; rr++) {
            int r = wid * 16 + rr;
            int m = m0 + r;
            int b = m >> 11;
            int s = m & 2047;

            float4 v = *(const float4*)&es[r * EROW + hp * 128 + lane * 4];

            float sq = v.x * v.x + v.y * v.y + v.z * v.z + v.w * v.w;
            #pragma unroll
            for (int o = 16; o; o >>= 1) sq += __shfl_xor_sync(0xffffffffu, sq, o);
            float inv = rsqrtf(sq * (1.0f / 128.0f) + 1e-6f);

            float4 xn = make_float4(v.x * inv * wv.x, v.y * inv * wv.y,
                                    v.z * inv * wv.z, v.w * inv * wv.w);

            float sgn = (lane < 16) ? -1.f : 1.f;
            float4 ot;
            ot.x = sgn * __shfl_xor_sync(0xffffffffu, xn.x, 16);
            ot.y = sgn * __shfl_xor_sync(0xffffffffu, xn.y, 16);
            ot.z = sgn * __shfl_xor_sync(0xffffffffu, xn.z, 16);
            ot.w = sgn * __shfl_xor_sync(0xffffffffu, xn.w, 16);

            size_t pidx = ((size_t)b * S_ + s) * D_ + lane * 4;
            float4 c = *(const float4*)(cosp + pidx);
            float4 sn = *(const float4*)(sinp + pidx);

            float r0 = (xn.x * c.x + ot.x * sn.x) * postscale;
            float r1 = (xn.y * c.y + ot.y * sn.y) * postscale;
            float r2 = (xn.z * c.z + ot.z * sn.z) * postscale;
            float r3 = (xn.w * c.w + ot.w * sn.w) * postscale;

            size_t off = ((size_t)(b * nh + hh) * S_ + s) * D_ + lane * 4;
            *(__half2*)(outp + off)     = __floats2half2_rn(r0, r1);
            *(__half2*)(outp + off + 2) = __floats2half2_rn(r2, r3);
        }
    }
}

// ---------------------------------------------------------------------------
// Causal flash attention: persistent CTAs + LPT work queue + max-free softmax.
// ---------------------------------------------------------------------------
#define FL_ROWB 272
#define FL_TILE (64 * FL_ROWB)       // 17408
#define FL_QOFF (4 * FL_TILE)
#define FL_SMEM (FL_QOFF + 128 * FL_ROWB)   // 104448
#define FL_GRID 296

__global__ __launch_bounds__(256, 2)
void flash16()
{
    extern __shared__ char fsm2[];
    __shared__ int s_item;
    const uint32_t sb = smem_to_u32(fsm2);
    const int tid = threadIdx.x;
    const int wid = tid >> 5, lane = tid & 31;

    const uint32_t qfb = sb + FL_QOFF + (wid * 16 + (lane & 15)) * FL_ROWB
                       + ((lane >> 4) << 4);
    const uint32_t kfbo = ((lane & 7) + ((lane >> 4) << 3)) * FL_ROWB
                        + (((lane >> 3) & 1) << 4);
    const uint32_t vfbo = (lane & 15) * FL_ROWB + ((lane >> 4) << 4);

    for (;;) {
        if (tid == 0) s_item = atomicAdd(&g_fctr, 1);
        __syncthreads();
        const int item = s_item;
        if (item >= NITEMS) break;

        const int qt = (NQT - 1) - (item >> 5);
        const int sub = item & 31;
        const int h = sub >> 1;
        const int b = sub & 1;
        const int kvh = h / GROUPS;
        const int qb = qt * 128;

        const __half* qg = g_qh + ((size_t)(b * H_ + h) * S_ + qb) * D_;
        const __half* kg = g_kh + ((size_t)(b * KV_ + kvh) * S_) * D_;
        const __half* vg = g_vh + ((size_t)(b * KV_ + kvh) * S_) * D_;

        #pragma unroll
        for (int u = 0; u < 8; u++) {
            int f = tid + u * 256;
            int r = f >> 4, cg = f & 15;
            cp_async16(sb + FL_QOFF + r * FL_ROWB + cg * 16, qg + (size_t)r * D_ + cg * 8);
        }
        CP_COMMIT();

        float oacc[16][4];
        #pragma unroll
        for (int i = 0; i < 16; i++)
            #pragma unroll
            for (int j = 0; j < 4; j++) oacc[i][j] = 0.f;
        float l_[2] = { 0.f, 0.f };

        const int nkt = 2 * qt + 2;

        auto load_kv = [&](int st, int kt) {
            const uint32_t off = sb + (uint32_t)(st * 2 * FL_TILE);
            const __half* kp = kg + (size_t)(kt * 64) * D_;
            const __half* vp = vg + (size_t)(kt * 64) * D_;
            #pragma unroll
            for (int u = 0; u < 4; u++) {
                int f = tid + u * 256;
                int r = f >> 4, cg = f & 15;
                cp_async16(off + r * FL_ROWB + cg * 16, kp + (size_t)r * D_ + cg * 8);
            }
            #pragma unroll
            for (int u = 0; u < 4; u++) {
                int f = tid + u * 256;
                int r = f >> 4, cg = f & 15;
                cp_async16(off + FL_TILE + r * FL_ROWB + cg * 16, vp + (size_t)r * D_ + cg * 8);
            }
        };

        load_kv(0, 0);
        CP_COMMIT();

        for (int kt = 0; kt < nkt; kt++) {
            CP_WAIT0();
            __syncthreads();
            if (kt + 1 < nkt) {
                load_kv((kt + 1) & 1, kt + 1);
                CP_COMMIT();
            }

            const uint32_t kbuf = sb + (uint32_t)((kt & 1) * 2 * FL_TILE);
            const uint32_t vbuf = kbuf + FL_TILE;

            float sacc[8][4];
            #pragma unroll
            for (int i = 0; i < 8; i++)
                #pragma unroll
                for (int j = 0; j < 4; j++) sacc[i][j] = 0.f;

            const uint32_t kfb = kbuf + kfbo;
            #pragma unroll
            for (int k8 = 0; k8 < 8; k8++) {
                uint32_t qa[4];
                LDSM_X4(qa, qfb + k8 * 32);
                #pragma unroll
                for (int np = 0; np < 4; np++) {
                    uint32_t r[4];
                    LDSM_X4(r, kfb + np * (16 * FL_ROWB) + k8 * 32);
                    mma_f16(sacc[2 * np],     qa, r[0], r[1]);
                    mma_f16(sacc[2 * np + 1], qa, r[2], r[3]);
                }
            }

            if (kt >= 2 * qt) {
                const int row0 = qb + wid * 16 + (lane >> 2);
                #pragma unroll
                for (int nt = 0; nt < 8; nt++) {
                    int c0 = kt * 64 + nt * 8 + 2 * (lane & 3);
                    if (c0 > row0)         sacc[nt][0] = -1e30f;
                    if (c0 + 1 > row0)     sacc[nt][1] = -1e30f;
                    if (c0 > row0 + 8)     sacc[nt][2] = -1e30f;
                    if (c0 + 1 > row0 + 8) sacc[nt][3] = -1e30f;
                }
            }

            // max-free softmax: p = exp(s - 2), logits provably <= 11.31
            float rs0 = 0.f, rs1 = 0.f;
            uint32_t pa[4][4];
            #pragma unroll
            for (int kg2 = 0; kg2 < 4; kg2++) {
                float p00 = __expf(sacc[2 * kg2][0] - 2.0f);
                float p01 = __expf(sacc[2 * kg2][1] - 2.0f);
                float p02 = __expf(sacc[2 * kg2][2] - 2.0f);
                float p03 = __expf(sacc[2 * kg2][3] - 2.0f);
                float p10 = __expf(sacc[2 * kg2 + 1][0] - 2.0f);
                float p11 = __expf(sacc[2 * kg2 + 1][1] - 2.0f);
                float p12 = __expf(sacc[2 * kg2 + 1][2] - 2.0f);
                float p13 = __expf(sacc[2 * kg2 + 1][3] - 2.0f);
                rs0 += p00 + p01 + p10 + p11;
                rs1 += p02 + p03 + p12 + p13;
                pa[kg2][0] = pack_half2(p00, p01);
                pa[kg2][1] = pack_half2(p02, p03);
                pa[kg2][2] = pack_half2(p10, p11);
                pa[kg2][3] = pack_half2(p12, p13);
            }
            rs0 += __shfl_xor_sync(0xffffffffu, rs0, 1);
            rs0 += __shfl_xor_sync(0xffffffffu, rs0, 2);
            rs1 += __shfl_xor_sync(0xffffffffu, rs1, 1);
            rs1 += __shfl_xor_sync(0xffffffffu, rs1, 2);
            l_[0] += rs0;
            l_[1] += rs1;

            const uint32_t vfb = vbuf + vfbo;
            #pragma unroll
            for (int kg2 = 0; kg2 < 4; kg2++) {
                #pragma unroll
                for (int np = 0; np < 8; np++) {
                    uint32_t r[4];
                    LDSM_X4_T(r, vfb + kg2 * (16 * FL_ROWB) + np * 32);
                    mma_f16(oacc[2 * np],     pa[kg2], r[0], r[1]);
                    mma_f16(oacc[2 * np + 1], pa[kg2], r[2], r[3]);
                }
            }
        }

        // epilogue: normalize -> fp16 plane [B,S,H,D]
        float inv0 = 1.f / l_[0], inv1 = 1.f / l_[1];
        int s0 = qb + wid * 16 + (lane >> 2);
        size_t o0 = ((size_t)(b * S_ + s0) * H_ + h) * D_;
        size_t o1 = o0 + (size_t)8 * H_ * D_;
        int dc = 2 * (lane & 3);
        #pragma unroll
        for (int nt = 0; nt < 16; nt++) {
            int d = nt * 8 + dc;
            *(__half2*)(g_atth + o0 + d) =
                __floats2half2_rn(oacc[nt][0] * inv0, oacc[nt][1] * inv0);
            *(__half2*)(g_atth + o1 + d) =
                __floats2half2_rn(oacc[nt][2] * inv1, oacc[nt][3] * inv1);
        }
    }
}

// ---------------------------------------------------------------------------
// kernel_launch
// Inputs: x, sin, cos, attention_mask, Wq, Wk, Wv, Wo, q_norm_w, k_norm_w
// ---------------------------------------------------------------------------
extern "C" void kernel_launch(void* const* d_in, const int* in_sizes, int n_in,
                              void* d_out, int out_size)
{
    const float* x    = (const float*)d_in[0];
    const float* sinp = (const float*)d_in[1];
    const float* cosp = (const float*)d_in[2];
    const float* Wq   = (const float*)d_in[4];
    const float* Wk   = (const float*)d_in[5];
    const float* Wv   = (const float*)d_in[6];
    const float* Wo   = (const float*)d_in[7];
    const float* qw   = (const float*)d_in[8];
    const float* kw   = (const float*)d_in[9];
    float* out = (float*)d_out;

    const int M = MROWS;   // 4096

    static __half *xh = nullptr, *atth = nullptr;
    static __half *wallh = nullptr, *woh = nullptr;
    if (!xh) {
        cudaGetSymbolAddress((void**)&xh, g_xh);
        cudaGetSymbolAddress((void**)&atth, g_atth);
        cudaGetSymbolAddress((void**)&wallh, g_wallh);
        cudaGetSymbolAddress((void**)&woh, g_woh);
    }

    // fused prep: x -> fp16 + all weight transposes + flash counter reset
    prep_all<<<20480, dim3(32, 8)>>>(
        x, xh,
        Wq, wallh,
        Wk, wallh + (size_t)(H_ * D_) * HID_,
        Wv, wallh + (size_t)((H_ + KV_) * D_) * HID_,
        Wo, woh);

    cudaFuncSetAttribute(gemm_f16, cudaFuncAttributeMaxDynamicSharedMemorySize, GEMM_SMEM);

    // fused QKV projection with in-epilogue RMSNorm + RoPE (CTA 128x256)
    gemm_f16<<<dim3(NQKV / BN, M / BM), 256, GEMM_SMEM>>>(
        xh, wallh, nullptr, M, NQKV, HID_, 4, qw, kw, sinp, cosp);

    // causal flash attention (persistent LPT queue, max-free softmax)
    cudaFuncSetAttribute(flash16, cudaFuncAttributeMaxDynamicSharedMemorySize, FL_SMEM);
    flash16<<<FL_GRID, 256, FL_SMEM>>>();

    // output projection — single-pass fp16 (CTA 128x256)
    gemm_f16<<<dim3(HID_ / BN, M / BM), 256, GEMM_SMEM>>>(
        atth, woh, out, M, HID_, H_ * D_, 0, nullptr, nullptr, nullptr, nullptr);
}